// round 2
// baseline (speedup 1.0000x reference)
#include <cuda_runtime.h>

#define N_NODES   50000
#define N_EDGES   800000
#define NUM_GRAPHS 512
#define F1 128
#define F2 64

// ---------------- scratch (device globals: allocation-free) ----------------
__device__ int   g_degi[N_NODES];
__device__ int   g_rowstart[N_NODES + 1];
__device__ int   g_cursor[N_NODES];
__device__ int   g_adj[N_EDGES];
__device__ float g_dinv[N_NODES];
__device__ float g_hs1[(size_t)N_NODES * F1];   // dinv * (x@W1)
__device__ float g_agg1[(size_t)N_NODES * F1];
__device__ float g_hs2[(size_t)N_NODES * F2];   // dinv * (relu(agg1)@W2)
__device__ float g_pool[NUM_GRAPHS * F2];
__device__ float g_cnt[NUM_GRAPHS];
__device__ int   g_src[N_EDGES];
__device__ int   g_dst[N_EDGES];
__device__ int   g_batch[N_NODES];
__device__ int   g_is64_edge;
__device__ int   g_is64_batch;

// ---------------- detect dtype (int64 vs int32) + zero scratch ----------------
__global__ void detect_zero_kernel(const int* __restrict__ ei32,
                                   const int* __restrict__ b32) {
    int i = blockIdx.x * blockDim.x + threadIdx.x;
    if (i < N_NODES)          g_degi[i] = 0;
    if (i < NUM_GRAPHS * F2)  g_pool[i] = 0.0f;
    if (i < NUM_GRAPHS)       g_cnt[i]  = 0.0f;

    if (blockIdx.x == 0) {
        __shared__ int s_e, s_b;
        if (threadIdx.x == 0) { s_e = 0; s_b = 0; }
        __syncthreads();
        int t = threadIdx.x;
        long long ie = (long long)t * 3121 + 5;      // < N_EDGES
        if (ei32[2 * ie + 1] != 0) atomicOr(&s_e, 1);
        long long ib = N_NODES / 2 - 1 - t;
        if (b32[2 * ib + 1] != 0) atomicOr(&s_b, 1);
        __syncthreads();
        if (threadIdx.x == 0) {
            g_is64_edge  = s_e ? 0 : 1;
            g_is64_batch = s_b ? 0 : 1;
        }
    }
}

// ---------------- convert indices, count degrees, count graph sizes ----------------
__global__ void convert_kernel(const int* __restrict__ ei32,
                               const int* __restrict__ b32) {
    int i = blockIdx.x * blockDim.x + threadIdx.x;
    int e64 = g_is64_edge, b64 = g_is64_batch;
    if (i < N_EDGES) {
        int s = e64 ? ei32[2 * (size_t)i]             : ei32[i];
        int d = e64 ? ei32[2 * ((size_t)N_EDGES + i)] : ei32[N_EDGES + i];
        g_src[i] = s;
        g_dst[i] = d;
        atomicAdd(&g_degi[d], 1);
    }
    if (i < N_NODES) {
        int b = b64 ? b32[2 * (size_t)i] : b32[i];
        g_batch[i] = b;
        atomicAdd(&g_cnt[b], 1.0f);
    }
}

// ---------------- single-block exclusive scan of degrees -> CSR row starts ----------------
__global__ void scan_kernel() {
    const int T = 1024;
    const int CH = (N_NODES + T - 1) / T;   // 49
    __shared__ int ssum[T];
    int t = threadIdx.x;
    int base = t * CH;
    int s = 0;
    for (int i = 0; i < CH; i++) {
        int idx = base + i;
        if (idx < N_NODES) s += g_degi[idx];
    }
    ssum[t] = s;
    __syncthreads();
    for (int off = 1; off < T; off <<= 1) {
        int v = (t >= off) ? ssum[t - off] : 0;
        __syncthreads();
        ssum[t] += v;
        __syncthreads();
    }
    int run = ssum[t] - s;     // exclusive prefix for this thread's chunk
    for (int i = 0; i < CH; i++) {
        int idx = base + i;
        if (idx < N_NODES) {
            g_rowstart[idx] = run;
            g_cursor[idx]   = run;
            int d = g_degi[idx];
            run += d;
            g_dinv[idx] = rsqrtf((float)(d + 1));   // +1 self loop
        }
    }
    if (t == T - 1) g_rowstart[N_NODES] = N_EDGES;
}

// ---------------- scatter edges into CSR adjacency ----------------
__global__ void scatter_kernel() {
    int i = blockIdx.x * blockDim.x + threadIdx.x;
    if (i >= N_EDGES) return;
    int pos = atomicAdd(&g_cursor[g_dst[i]], 1);
    g_adj[pos] = g_src[i];
}

// ---------------- GEMM: C[M,N] = dinv[row] * op(A[M,128]) @ W[128,N] ----------------
template <int N, int BM, bool RELU>
__global__ void gemm_kernel(const float* __restrict__ A,
                            const float* __restrict__ W,
                            float* __restrict__ C, int M) {
    constexpr int K  = 128;
    constexpr int XP = K + 4;
    constexpr int NT = (N / 4) * (BM / 4);
    extern __shared__ float sm[];
    float* Ws = sm;                  // K*N
    float* Xs = sm + K * N;          // BM*XP

    int tid = threadIdx.x;
    const float4* W4 = (const float4*)W;
    float4* Ws4w = (float4*)Ws;
    #pragma unroll
    for (int idx = tid; idx < K * N / 4; idx += NT) Ws4w[idx] = W4[idx];

    int row0 = blockIdx.x * BM;
    for (int idx = tid; idx < BM * 32; idx += NT) {
        int r  = idx >> 5;
        int k4 = idx & 31;
        int row = row0 + r;
        float4 v = make_float4(0.f, 0.f, 0.f, 0.f);
        if (row < M) v = ((const float4*)A)[(size_t)row * 32 + k4];
        if (RELU) {
            v.x = fmaxf(v.x, 0.f); v.y = fmaxf(v.y, 0.f);
            v.z = fmaxf(v.z, 0.f); v.w = fmaxf(v.w, 0.f);
        }
        *(float4*)&Xs[r * XP + k4 * 4] = v;
    }
    __syncthreads();

    int nc = tid % (N / 4);
    int rg = tid / (N / 4);
    float acc[4][4];
    #pragma unroll
    for (int i = 0; i < 4; i++)
        #pragma unroll
        for (int j = 0; j < 4; j++) acc[i][j] = 0.f;

    const float4* Ws4 = (const float4*)Ws;
    #pragma unroll 4
    for (int k = 0; k < K; k++) {
        float4 w = Ws4[k * (N / 4) + nc];
        float xr[4];
        #pragma unroll
        for (int i = 0; i < 4; i++) xr[i] = Xs[(rg * 4 + i) * XP + k];
        #pragma unroll
        for (int i = 0; i < 4; i++) {
            acc[i][0] += xr[i] * w.x;
            acc[i][1] += xr[i] * w.y;
            acc[i][2] += xr[i] * w.z;
            acc[i][3] += xr[i] * w.w;
        }
    }

    #pragma unroll
    for (int i = 0; i < 4; i++) {
        int row = row0 + rg * 4 + i;
        if (row < M) {
            float dv = g_dinv[row];
            float4 o = make_float4(acc[i][0] * dv, acc[i][1] * dv,
                                   acc[i][2] * dv, acc[i][3] * dv);
            ((float4*)C)[(size_t)row * (N / 4) + nc] = o;
        }
    }
}

// ---------------- layer1 gather: agg1[v] = b1 + dinv[v]*(hs1[v] + sum hs1[adj]) ----------------
__global__ void gather128_kernel(const float* __restrict__ hs,
                                 const float* __restrict__ bias,
                                 float* __restrict__ agg) {
    int gtid = blockIdx.x * blockDim.x + threadIdx.x;
    int v    = gtid >> 5;
    int lane = threadIdx.x & 31;
    if (v >= N_NODES) return;
    int rs = 0, re = 0; float dv = 0.f;
    if (lane == 0) {
        rs = g_rowstart[v];
        re = g_rowstart[v + 1];
        dv = g_dinv[v];
    }
    rs = __shfl_sync(0xffffffffu, rs, 0);
    re = __shfl_sync(0xffffffffu, re, 0);
    dv = __shfl_sync(0xffffffffu, dv, 0);

    const float4* hs4 = (const float4*)hs;
    float4 acc = hs4[(size_t)v * 32 + lane];   // self loop
    int i = rs;
    for (; i + 2 <= re; i += 2) {
        int u0 = g_adj[i], u1 = g_adj[i + 1];
        float4 a = hs4[(size_t)u0 * 32 + lane];
        float4 b = hs4[(size_t)u1 * 32 + lane];
        acc.x += a.x + b.x; acc.y += a.y + b.y;
        acc.z += a.z + b.z; acc.w += a.w + b.w;
    }
    if (i < re) {
        int u = g_adj[i];
        float4 a = hs4[(size_t)u * 32 + lane];
        acc.x += a.x; acc.y += a.y; acc.z += a.z; acc.w += a.w;
    }
    float4 bb = ((const float4*)bias)[lane];
    float4 o = make_float4(bb.x + dv * acc.x, bb.y + dv * acc.y,
                           bb.z + dv * acc.z, bb.w + dv * acc.w);
    ((float4*)agg)[(size_t)v * 32 + lane] = o;
}

__device__ __forceinline__ void red_add_v4(float* p, float4 v) {
    asm volatile("red.global.add.v4.f32 [%0], {%1,%2,%3,%4};"
                 :: "l"(p), "f"(v.x), "f"(v.y), "f"(v.z), "f"(v.w)
                 : "memory");
}

// ---------------- layer2 gather + pool: pool[batch[v]] += b2 + dinv*(hs2[v]+sum) ----------------
__global__ void gather64_pool_kernel(const float* __restrict__ hs,
                                     const float* __restrict__ bias) {
    int gtid = blockIdx.x * blockDim.x + threadIdx.x;
    int v    = gtid >> 4;
    int sub  = threadIdx.x & 15;
    if (v >= N_NODES) return;
    int rs = 0, re = 0, g = 0; float dv = 0.f;
    if (sub == 0) {
        rs = g_rowstart[v];
        re = g_rowstart[v + 1];
        dv = g_dinv[v];
        g  = g_batch[v];
    }
    rs = __shfl_sync(0xffffffffu, rs, 0, 16);
    re = __shfl_sync(0xffffffffu, re, 0, 16);
    dv = __shfl_sync(0xffffffffu, dv, 0, 16);
    g  = __shfl_sync(0xffffffffu, g, 0, 16);

    const float4* hs4 = (const float4*)hs;
    float4 acc = hs4[(size_t)v * 16 + sub];    // self loop
    int i = rs;
    for (; i + 2 <= re; i += 2) {
        int u0 = g_adj[i], u1 = g_adj[i + 1];
        float4 a = hs4[(size_t)u0 * 16 + sub];
        float4 b = hs4[(size_t)u1 * 16 + sub];
        acc.x += a.x + b.x; acc.y += a.y + b.y;
        acc.z += a.z + b.z; acc.w += a.w + b.w;
    }
    if (i < re) {
        int u = g_adj[i];
        float4 a = hs4[(size_t)u * 16 + sub];
        acc.x += a.x; acc.y += a.y; acc.z += a.z; acc.w += a.w;
    }
    float4 bb = ((const float4*)bias)[sub];
    float4 o = make_float4(bb.x + dv * acc.x, bb.y + dv * acc.y,
                           bb.z + dv * acc.z, bb.w + dv * acc.w);
    red_add_v4(g_pool + (size_t)g * 64 + sub * 4, o);
}

// ---------------- final: out = (pool / max(cnt,1)) @ Wl + bl ----------------
__global__ void final_kernel(const float* __restrict__ Wl,
                             const float* __restrict__ bl,
                             float* __restrict__ out) {
    int g = blockIdx.x;
    int n = threadIdx.x;
    __shared__ float ps[64];
    float inv = 1.0f / fmaxf(g_cnt[g], 1.0f);
    ps[n] = g_pool[g * 64 + n] * inv;
    __syncthreads();
    float acc = bl[n];
    #pragma unroll
    for (int k = 0; k < 64; k++) acc += ps[k] * Wl[k * 64 + n];
    out[g * 64 + n] = acc;
}

// ---------------- launch ----------------
extern "C" void kernel_launch(void* const* d_in, const int* in_sizes, int n_in,
                              void* d_out, int out_size) {
    const float* x    = (const float*)d_in[0];
    const int*   ei32 = (const int*)d_in[1];
    const int*   b32  = (const int*)d_in[2];
    const float* W1   = (const float*)d_in[3];
    const float* b1   = (const float*)d_in[4];
    const float* W2   = (const float*)d_in[5];
    const float* b2   = (const float*)d_in[6];
    const float* Wl   = (const float*)d_in[7];
    const float* bl   = (const float*)d_in[8];
    float* out = (float*)d_out;

    float *p_hs1, *p_agg1, *p_hs2;
    cudaGetSymbolAddress((void**)&p_hs1,  g_hs1);
    cudaGetSymbolAddress((void**)&p_agg1, g_agg1);
    cudaGetSymbolAddress((void**)&p_hs2,  g_hs2);

    const int SM_G1 = (128 * 128 + 32 * 132) * 4;   // 82432
    const int SM_G2 = (128 * 64 + 64 * 132) * 4;    // 66560
    cudaFuncSetAttribute((const void*)gemm_kernel<128, 32, false>,
                         cudaFuncAttributeMaxDynamicSharedMemorySize, SM_G1);
    cudaFuncSetAttribute((const void*)gemm_kernel<64, 64, true>,
                         cudaFuncAttributeMaxDynamicSharedMemorySize, SM_G2);

    // CSR build
    detect_zero_kernel<<<(N_NODES + 255) / 256, 256>>>(ei32, b32);
    convert_kernel<<<(N_EDGES + 255) / 256, 256>>>(ei32, b32);
    scan_kernel<<<1, 1024>>>();
    scatter_kernel<<<(N_EDGES + 255) / 256, 256>>>();

    // layer 1
    gemm_kernel<128, 32, false><<<(N_NODES + 31) / 32, 256, SM_G1>>>(x, W1, p_hs1, N_NODES);
    gather128_kernel<<<(N_NODES * 32 + 255) / 256, 256>>>(p_hs1, b1, p_agg1);

    // layer 2 (+ fused pool)
    gemm_kernel<64, 64, true><<<(N_NODES + 63) / 64, 256, SM_G2>>>(p_agg1, W2, p_hs2, N_NODES);
    gather64_pool_kernel<<<(N_NODES * 16 + 255) / 256, 256>>>(p_hs2, b2);

    // final linear
    final_kernel<<<NUM_GRAPHS, 64>>>(Wl, bl, out);
}

// round 3
// speedup vs baseline: 1.5714x; 1.5714x over previous
#include <cuda_runtime.h>

#define N_NODES   50000
#define N_EDGES   800000
#define NUM_GRAPHS 512
#define F1 128
#define F2 64
#define NBLK 196   // ceil(N_NODES/256)

typedef unsigned long long u64;

// ---------------- scratch (device globals: allocation-free) ----------------
__device__ int   g_degi[N_NODES];
__device__ int   g_rowstart[N_NODES + 1];
__device__ int   g_cursor[N_NODES];
__device__ int   g_adj[N_EDGES];
__device__ int   g_blocksum[NBLK];
__device__ int   g_blockoff[NBLK];
__device__ float g_dinv[N_NODES];
__device__ float g_hs1[(size_t)N_NODES * F1];   // dinv * (x@W1)
__device__ float g_agg1[(size_t)N_NODES * F1];
__device__ float g_hs2[(size_t)N_NODES * F2];   // dinv * (relu(agg1)@W2)
__device__ float g_pool[NUM_GRAPHS * F2];
__device__ float g_cnt[NUM_GRAPHS];
__device__ int   g_src[N_EDGES];
__device__ int   g_dst[N_EDGES];
__device__ int   g_batch[N_NODES];
__device__ int   g_is64_edge;
__device__ int   g_is64_batch;

// ---------------- f32x2 helpers ----------------
__device__ __forceinline__ u64 pack2(float x) {
    u64 r; asm("mov.b64 %0, {%1, %1};" : "=l"(r) : "f"(x)); return r;
}
__device__ __forceinline__ void ffma2(u64& d, u64 a, u64 b) {
    asm("fma.rn.f32x2 %0, %1, %2, %0;" : "+l"(d) : "l"(a), "l"(b));
}
__device__ __forceinline__ float2 unpack2(u64 v) {
    float2 r; asm("mov.b64 {%0, %1}, %2;" : "=f"(r.x), "=f"(r.y) : "l"(v)); return r;
}

// ---------------- detect dtype (int64 vs int32) + zero scratch ----------------
__global__ void detect_zero_kernel(const int* __restrict__ ei32,
                                   const int* __restrict__ b32) {
    int i = blockIdx.x * blockDim.x + threadIdx.x;
    if (i < N_NODES)          g_degi[i] = 0;
    if (i < NUM_GRAPHS * F2)  g_pool[i] = 0.0f;
    if (i < NUM_GRAPHS)       g_cnt[i]  = 0.0f;

    if (blockIdx.x == 0) {
        __shared__ int s_e, s_b;
        if (threadIdx.x == 0) { s_e = 0; s_b = 0; }
        __syncthreads();
        int t = threadIdx.x;
        long long ie = (long long)t * 3121 + 5;      // < N_EDGES
        if (ei32[2 * ie + 1] != 0) atomicOr(&s_e, 1);
        long long ib = N_NODES / 2 - 1 - t;
        if (b32[2 * ib + 1] != 0) atomicOr(&s_b, 1);
        __syncthreads();
        if (threadIdx.x == 0) {
            g_is64_edge  = s_e ? 0 : 1;
            g_is64_batch = s_b ? 0 : 1;
        }
    }
}

// ---------------- convert indices, count degrees, count graph sizes ----------------
__global__ void convert_kernel(const int* __restrict__ ei32,
                               const int* __restrict__ b32) {
    int i = blockIdx.x * blockDim.x + threadIdx.x;
    int e64 = g_is64_edge, b64 = g_is64_batch;
    if (i < N_EDGES) {
        int s = e64 ? ei32[2 * (size_t)i]             : ei32[i];
        int d = e64 ? ei32[2 * ((size_t)N_EDGES + i)] : ei32[N_EDGES + i];
        g_src[i] = s;
        g_dst[i] = d;
        atomicAdd(&g_degi[d], 1);
    }
    if (i < N_NODES) {
        int b = b64 ? b32[2 * (size_t)i] : b32[i];
        g_batch[i] = b;
        atomicAdd(&g_cnt[b], 1.0f);
    }
}

// ---------------- 3-phase coalesced exclusive scan ----------------
__global__ void scanA_kernel() {     // per-block sums
    __shared__ int sh[256];
    int idx = blockIdx.x * 256 + threadIdx.x;
    int d = (idx < N_NODES) ? g_degi[idx] : 0;
    sh[threadIdx.x] = d;
    __syncthreads();
    #pragma unroll
    for (int off = 128; off > 0; off >>= 1) {
        if (threadIdx.x < off) sh[threadIdx.x] += sh[threadIdx.x + off];
        __syncthreads();
    }
    if (threadIdx.x == 0) g_blocksum[blockIdx.x] = sh[0];
}

__global__ void scanB_kernel() {     // scan 196 block sums
    __shared__ int sh[256];
    int t = threadIdx.x;
    int v = (t < NBLK) ? g_blocksum[t] : 0;
    sh[t] = v;
    __syncthreads();
    #pragma unroll
    for (int off = 1; off < 256; off <<= 1) {
        int u = (t >= off) ? sh[t - off] : 0;
        __syncthreads();
        sh[t] += u;
        __syncthreads();
    }
    if (t < NBLK) g_blockoff[t] = sh[t] - v;
}

__global__ void scanC_kernel() {     // emit rowstart/cursor/dinv
    __shared__ int sh[256];
    int idx = blockIdx.x * 256 + threadIdx.x;
    int t = threadIdx.x;
    int d = (idx < N_NODES) ? g_degi[idx] : 0;
    sh[t] = d;
    __syncthreads();
    #pragma unroll
    for (int off = 1; off < 256; off <<= 1) {
        int u = (t >= off) ? sh[t - off] : 0;
        __syncthreads();
        sh[t] += u;
        __syncthreads();
    }
    if (idx < N_NODES) {
        int excl = g_blockoff[blockIdx.x] + sh[t] - d;
        g_rowstart[idx] = excl;
        g_cursor[idx]   = excl;
        g_dinv[idx]     = rsqrtf((float)(d + 1));   // +1 self loop
        if (idx == N_NODES - 1) g_rowstart[N_NODES] = N_EDGES;
    }
}

// ---------------- scatter edges into CSR adjacency ----------------
__global__ void scatter_kernel() {
    int i = blockIdx.x * blockDim.x + threadIdx.x;
    if (i >= N_EDGES) return;
    int pos = atomicAdd(&g_cursor[g_dst[i]], 1);
    g_adj[pos] = g_src[i];
}

// ---------------- GEMM: C[M,N] = dinv[row] * op(A[M,128]) @ W[128,N] ----------------
// f32x2-packed microtile: each thread computes 4 rows x 4 cols (as 4x2 f32x2).
template <int N, int BM, bool RELU>
__global__ void gemm_kernel(const float* __restrict__ A,
                            const float* __restrict__ W,
                            float* __restrict__ C, int M) {
    constexpr int K  = 128;
    constexpr int XP = K + 4;
    constexpr int NT = (N / 4) * (BM / 4);
    extern __shared__ float sm[];
    float* Ws = sm;                  // K*N
    float* Xs = sm + K * N;          // BM*XP

    int tid = threadIdx.x;
    const float4* W4 = (const float4*)W;
    float4* Ws4w = (float4*)Ws;
    #pragma unroll
    for (int idx = tid; idx < K * N / 4; idx += NT) Ws4w[idx] = W4[idx];

    int row0 = blockIdx.x * BM;
    for (int idx = tid; idx < BM * 32; idx += NT) {
        int r  = idx >> 5;
        int k4 = idx & 31;
        int row = row0 + r;
        float4 v = make_float4(0.f, 0.f, 0.f, 0.f);
        if (row < M) v = ((const float4*)A)[(size_t)row * 32 + k4];
        if (RELU) {
            v.x = fmaxf(v.x, 0.f); v.y = fmaxf(v.y, 0.f);
            v.z = fmaxf(v.z, 0.f); v.w = fmaxf(v.w, 0.f);
        }
        *(float4*)&Xs[r * XP + k4 * 4] = v;
    }
    __syncthreads();

    int nc = tid % (N / 4);
    int rg = tid / (N / 4);
    u64 acc[4][2];
    #pragma unroll
    for (int i = 0; i < 4; i++) { acc[i][0] = 0ull; acc[i][1] = 0ull; }

    #pragma unroll 4
    for (int k = 0; k < K; k++) {
        // w pair-of-pairs: (w0,w1),(w2,w3) for this thread's 4 columns
        ulonglong2 wp = ((const ulonglong2*)(Ws + k * N))[nc];
        #pragma unroll
        for (int i = 0; i < 4; i++) {
            u64 xp = pack2(Xs[(rg * 4 + i) * XP + k]);
            ffma2(acc[i][0], xp, wp.x);
            ffma2(acc[i][1], xp, wp.y);
        }
    }

    #pragma unroll
    for (int i = 0; i < 4; i++) {
        int row = row0 + rg * 4 + i;
        if (row < M) {
            float dv = g_dinv[row];
            float2 a = unpack2(acc[i][0]);
            float2 b = unpack2(acc[i][1]);
            float4 o = make_float4(a.x * dv, a.y * dv, b.x * dv, b.y * dv);
            ((float4*)C)[(size_t)row * (N / 4) + nc] = o;
        }
    }
}

// ---------------- layer1 gather: agg1[v] = b1 + dinv[v]*(hs1[v] + sum hs1[adj]) ----------------
__global__ void gather128_kernel(const float* __restrict__ hs,
                                 const float* __restrict__ bias,
                                 float* __restrict__ agg) {
    int gtid = blockIdx.x * blockDim.x + threadIdx.x;
    int v    = gtid >> 5;
    int lane = threadIdx.x & 31;
    if (v >= N_NODES) return;
    int rs = 0, re = 0; float dv = 0.f;
    if (lane == 0) {
        rs = g_rowstart[v];
        re = g_rowstart[v + 1];
        dv = g_dinv[v];
    }
    rs = __shfl_sync(0xffffffffu, rs, 0);
    re = __shfl_sync(0xffffffffu, re, 0);
    dv = __shfl_sync(0xffffffffu, dv, 0);

    const float4* hs4 = (const float4*)hs;
    float4 acc = hs4[(size_t)v * 32 + lane];   // self loop
    int i = rs;
    for (; i + 4 <= re; i += 4) {
        int u0 = g_adj[i],     u1 = g_adj[i + 1];
        int u2 = g_adj[i + 2], u3 = g_adj[i + 3];
        float4 a = hs4[(size_t)u0 * 32 + lane];
        float4 b = hs4[(size_t)u1 * 32 + lane];
        float4 c = hs4[(size_t)u2 * 32 + lane];
        float4 d = hs4[(size_t)u3 * 32 + lane];
        acc.x += (a.x + b.x) + (c.x + d.x);
        acc.y += (a.y + b.y) + (c.y + d.y);
        acc.z += (a.z + b.z) + (c.z + d.z);
        acc.w += (a.w + b.w) + (c.w + d.w);
    }
    for (; i < re; i++) {
        int u = g_adj[i];
        float4 a = hs4[(size_t)u * 32 + lane];
        acc.x += a.x; acc.y += a.y; acc.z += a.z; acc.w += a.w;
    }
    float4 bb = ((const float4*)bias)[lane];
    float4 o = make_float4(bb.x + dv * acc.x, bb.y + dv * acc.y,
                           bb.z + dv * acc.z, bb.w + dv * acc.w);
    ((float4*)agg)[(size_t)v * 32 + lane] = o;
}

__device__ __forceinline__ void red_add_v4(float* p, float4 v) {
    asm volatile("red.global.add.v4.f32 [%0], {%1,%2,%3,%4};"
                 :: "l"(p), "f"(v.x), "f"(v.y), "f"(v.z), "f"(v.w)
                 : "memory");
}

// ---------------- layer2 gather + pool ----------------
__global__ void gather64_pool_kernel(const float* __restrict__ hs,
                                     const float* __restrict__ bias) {
    int gtid = blockIdx.x * blockDim.x + threadIdx.x;
    int v    = gtid >> 4;
    int sub  = threadIdx.x & 15;
    if (v >= N_NODES) return;
    int rs = 0, re = 0, g = 0; float dv = 0.f;
    if (sub == 0) {
        rs = g_rowstart[v];
        re = g_rowstart[v + 1];
        dv = g_dinv[v];
        g  = g_batch[v];
    }
    rs = __shfl_sync(0xffffffffu, rs, 0, 16);
    re = __shfl_sync(0xffffffffu, re, 0, 16);
    dv = __shfl_sync(0xffffffffu, dv, 0, 16);
    g  = __shfl_sync(0xffffffffu, g, 0, 16);

    const float4* hs4 = (const float4*)hs;
    float4 acc = hs4[(size_t)v * 16 + sub];    // self loop
    int i = rs;
    for (; i + 4 <= re; i += 4) {
        int u0 = g_adj[i],     u1 = g_adj[i + 1];
        int u2 = g_adj[i + 2], u3 = g_adj[i + 3];
        float4 a = hs4[(size_t)u0 * 16 + sub];
        float4 b = hs4[(size_t)u1 * 16 + sub];
        float4 c = hs4[(size_t)u2 * 16 + sub];
        float4 d = hs4[(size_t)u3 * 16 + sub];
        acc.x += (a.x + b.x) + (c.x + d.x);
        acc.y += (a.y + b.y) + (c.y + d.y);
        acc.z += (a.z + b.z) + (c.z + d.z);
        acc.w += (a.w + b.w) + (c.w + d.w);
    }
    for (; i < re; i++) {
        int u = g_adj[i];
        float4 a = hs4[(size_t)u * 16 + sub];
        acc.x += a.x; acc.y += a.y; acc.z += a.z; acc.w += a.w;
    }
    float4 bb = ((const float4*)bias)[sub];
    float4 o = make_float4(bb.x + dv * acc.x, bb.y + dv * acc.y,
                           bb.z + dv * acc.z, bb.w + dv * acc.w);
    red_add_v4(g_pool + (size_t)g * 64 + sub * 4, o);
}

// ---------------- final: out = (pool / max(cnt,1)) @ Wl + bl ----------------
__global__ void final_kernel(const float* __restrict__ Wl,
                             const float* __restrict__ bl,
                             float* __restrict__ out) {
    int g = blockIdx.x;
    int n = threadIdx.x;
    __shared__ float ps[64];
    float inv = 1.0f / fmaxf(g_cnt[g], 1.0f);
    ps[n] = g_pool[g * 64 + n] * inv;
    __syncthreads();
    float acc = bl[n];
    #pragma unroll
    for (int k = 0; k < 64; k++) acc += ps[k] * Wl[k * 64 + n];
    out[g * 64 + n] = acc;
}

// ---------------- launch ----------------
extern "C" void kernel_launch(void* const* d_in, const int* in_sizes, int n_in,
                              void* d_out, int out_size) {
    const float* x    = (const float*)d_in[0];
    const int*   ei32 = (const int*)d_in[1];
    const int*   b32  = (const int*)d_in[2];
    const float* W1   = (const float*)d_in[3];
    const float* b1   = (const float*)d_in[4];
    const float* W2   = (const float*)d_in[5];
    const float* b2   = (const float*)d_in[6];
    const float* Wl   = (const float*)d_in[7];
    const float* bl   = (const float*)d_in[8];
    float* out = (float*)d_out;

    float *p_hs1, *p_agg1, *p_hs2;
    cudaGetSymbolAddress((void**)&p_hs1,  g_hs1);
    cudaGetSymbolAddress((void**)&p_agg1, g_agg1);
    cudaGetSymbolAddress((void**)&p_hs2,  g_hs2);

    const int SM_G1 = (128 * 128 + 32 * 132) * 4;   // 82432
    const int SM_G2 = (128 * 64 + 64 * 132) * 4;    // 66560
    cudaFuncSetAttribute((const void*)gemm_kernel<128, 32, false>,
                         cudaFuncAttributeMaxDynamicSharedMemorySize, SM_G1);
    cudaFuncSetAttribute((const void*)gemm_kernel<64, 64, true>,
                         cudaFuncAttributeMaxDynamicSharedMemorySize, SM_G2);

    // CSR build
    detect_zero_kernel<<<NBLK, 256>>>(ei32, b32);
    convert_kernel<<<(N_EDGES + 255) / 256, 256>>>(ei32, b32);
    scanA_kernel<<<NBLK, 256>>>();
    scanB_kernel<<<1, 256>>>();
    scanC_kernel<<<NBLK, 256>>>();
    scatter_kernel<<<(N_EDGES + 255) / 256, 256>>>();

    // layer 1
    gemm_kernel<128, 32, false><<<(N_NODES + 31) / 32, 256, SM_G1>>>(x, W1, p_hs1, N_NODES);
    gather128_kernel<<<(N_NODES * 32 + 255) / 256, 256>>>(p_hs1, b1, p_agg1);

    // layer 2 (+ fused pool)
    gemm_kernel<64, 64, true><<<(N_NODES + 63) / 64, 256, SM_G2>>>(p_agg1, W2, p_hs2, N_NODES);
    gather64_pool_kernel<<<(N_NODES * 16 + 255) / 256, 256>>>(p_hs2, b2);

    // final linear
    final_kernel<<<NUM_GRAPHS, 64>>>(Wl, bl, out);
}

// round 4
// speedup vs baseline: 1.6270x; 1.0354x over previous
#include <cuda_runtime.h>

#define N_NODES   50000
#define N_EDGES   800000
#define NUM_GRAPHS 512
#define F1 128
#define F2 64
#define NBLK 196   // ceil(N_NODES/256)

typedef unsigned long long u64;

// ---------------- scratch (device globals: allocation-free) ----------------
__device__ int   g_degi[N_NODES];
__device__ int   g_rowstart[N_NODES + 1];
__device__ int   g_cursor[N_NODES];
__device__ int   g_adj[N_EDGES];
__device__ int   g_blocksum[NBLK];
__device__ float g_dinv[N_NODES];
__device__ float g_h1[(size_t)N_NODES * F1];    // x@W1 (unscaled)
__device__ float g_agg1[(size_t)N_NODES * F1];
__device__ float g_hs2[(size_t)N_NODES * F2];   // dinv * (relu(agg1)@W2)
__device__ float g_pool[NUM_GRAPHS * F2];
__device__ float g_cnt[NUM_GRAPHS];
__device__ int   g_src[N_EDGES];
__device__ int   g_dst[N_EDGES];
__device__ int   g_batch[N_NODES];
__device__ int   g_is64_edge;
__device__ int   g_is64_batch;

// ---------------- static side stream + events (host objects, created at load) ----------------
static cudaStream_t s_side;
static cudaEvent_t  s_ev_fork, s_ev_gemm1;
namespace {
struct StreamInit {
    StreamInit() {
        cudaStreamCreateWithFlags(&s_side, cudaStreamNonBlocking);
        cudaEventCreateWithFlags(&s_ev_fork,  cudaEventDisableTiming);
        cudaEventCreateWithFlags(&s_ev_gemm1, cudaEventDisableTiming);
    }
};
static StreamInit s_stream_init;
}

// ---------------- f32x2 helpers ----------------
__device__ __forceinline__ u64 pack2(float x) {
    u64 r; asm("mov.b64 %0, {%1, %1};" : "=l"(r) : "f"(x)); return r;
}
__device__ __forceinline__ void ffma2(u64& d, u64 a, u64 b) {
    asm("fma.rn.f32x2 %0, %1, %2, %0;" : "+l"(d) : "l"(a), "l"(b));
}
__device__ __forceinline__ float2 unpack2(u64 v) {
    float2 r; asm("mov.b64 {%0, %1}, %2;" : "=f"(r.x), "=f"(r.y) : "l"(v)); return r;
}

// ---------------- detect dtype (int64 vs int32) + zero scratch ----------------
__global__ void detect_zero_kernel(const int* __restrict__ ei32,
                                   const int* __restrict__ b32) {
    int i = blockIdx.x * blockDim.x + threadIdx.x;
    if (i < N_NODES)          g_degi[i] = 0;
    if (i < NUM_GRAPHS * F2)  g_pool[i] = 0.0f;
    if (i < NUM_GRAPHS)       g_cnt[i]  = 0.0f;

    if (blockIdx.x == 0) {
        __shared__ int s_e, s_b;
        if (threadIdx.x == 0) { s_e = 0; s_b = 0; }
        __syncthreads();
        int t = threadIdx.x;
        long long ie = (long long)t * 3121 + 5;      // < N_EDGES
        if (ei32[2 * ie + 1] != 0) atomicOr(&s_e, 1);
        long long ib = N_NODES / 2 - 1 - t;
        if (b32[2 * ib + 1] != 0) atomicOr(&s_b, 1);
        __syncthreads();
        if (threadIdx.x == 0) {
            g_is64_edge  = s_e ? 0 : 1;
            g_is64_batch = s_b ? 0 : 1;
        }
    }
}

// ---------------- convert indices, count degrees, count graph sizes ----------------
__global__ void convert_kernel(const int* __restrict__ ei32,
                               const int* __restrict__ b32) {
    int i = blockIdx.x * blockDim.x + threadIdx.x;
    int e64 = g_is64_edge, b64 = g_is64_batch;
    if (i < N_EDGES) {
        int s = e64 ? ei32[2 * (size_t)i]             : ei32[i];
        int d = e64 ? ei32[2 * ((size_t)N_EDGES + i)] : ei32[N_EDGES + i];
        g_src[i] = s;
        g_dst[i] = d;
        atomicAdd(&g_degi[d], 1);
    }
    if (i < N_NODES) {
        int b = b64 ? b32[2 * (size_t)i] : b32[i];
        g_batch[i] = b;
        atomicAdd(&g_cnt[b], 1.0f);
    }
}

// ---------------- 2-phase coalesced exclusive scan ----------------
__global__ void scanA_kernel() {     // per-block sums
    __shared__ int sh[256];
    int idx = blockIdx.x * 256 + threadIdx.x;
    int d = (idx < N_NODES) ? g_degi[idx] : 0;
    sh[threadIdx.x] = d;
    __syncthreads();
    #pragma unroll
    for (int off = 128; off > 0; off >>= 1) {
        if (threadIdx.x < off) sh[threadIdx.x] += sh[threadIdx.x + off];
        __syncthreads();
    }
    if (threadIdx.x == 0) g_blocksum[blockIdx.x] = sh[0];
}

__global__ void scanC_kernel() {     // per-block: block offset + local scan + emit
    __shared__ int soff[256];
    __shared__ int sh[256];
    int t = threadIdx.x;
    // block offset = sum of blocksum[0..blockIdx)
    int bs = (t < NBLK && t < blockIdx.x) ? g_blocksum[t] : 0;
    soff[t] = bs;
    __syncthreads();
    #pragma unroll
    for (int off = 128; off > 0; off >>= 1) {
        if (t < off) soff[t] += soff[t + off];
        __syncthreads();
    }
    int blockoff = soff[0];

    int idx = blockIdx.x * 256 + t;
    int d = (idx < N_NODES) ? g_degi[idx] : 0;
    sh[t] = d;
    __syncthreads();
    #pragma unroll
    for (int off = 1; off < 256; off <<= 1) {
        int u = (t >= off) ? sh[t - off] : 0;
        __syncthreads();
        sh[t] += u;
        __syncthreads();
    }
    if (idx < N_NODES) {
        int excl = blockoff + sh[t] - d;
        g_rowstart[idx] = excl;
        g_cursor[idx]   = excl;
        g_dinv[idx]     = rsqrtf((float)(d + 1));   // +1 self loop
        if (idx == N_NODES - 1) g_rowstart[N_NODES] = N_EDGES;
    }
}

// ---------------- scatter edges into CSR adjacency ----------------
__global__ void scatter_kernel() {
    int i = blockIdx.x * blockDim.x + threadIdx.x;
    if (i >= N_EDGES) return;
    int pos = atomicAdd(&g_cursor[g_dst[i]], 1);
    g_adj[pos] = g_src[i];
}

// ---------------- GEMM: C[M,N] = [dinv[row] *] op(A[M,128]) @ W[128,N] ----------------
template <int N, int BM, bool RELU, bool SCALE>
__global__ void gemm_kernel(const float* __restrict__ A,
                            const float* __restrict__ W,
                            float* __restrict__ C, int M) {
    constexpr int K  = 128;
    constexpr int XP = K + 4;
    constexpr int NT = (N / 4) * (BM / 4);
    extern __shared__ float sm[];
    float* Ws = sm;                  // K*N
    float* Xs = sm + K * N;          // BM*XP

    int tid = threadIdx.x;
    const float4* W4 = (const float4*)W;
    float4* Ws4w = (float4*)Ws;
    #pragma unroll
    for (int idx = tid; idx < K * N / 4; idx += NT) Ws4w[idx] = W4[idx];

    int row0 = blockIdx.x * BM;
    for (int idx = tid; idx < BM * 32; idx += NT) {
        int r  = idx >> 5;
        int k4 = idx & 31;
        int row = row0 + r;
        float4 v = make_float4(0.f, 0.f, 0.f, 0.f);
        if (row < M) v = ((const float4*)A)[(size_t)row * 32 + k4];
        if (RELU) {
            v.x = fmaxf(v.x, 0.f); v.y = fmaxf(v.y, 0.f);
            v.z = fmaxf(v.z, 0.f); v.w = fmaxf(v.w, 0.f);
        }
        *(float4*)&Xs[r * XP + k4 * 4] = v;
    }
    __syncthreads();

    int nc = tid % (N / 4);
    int rg = tid / (N / 4);
    u64 acc[4][2];
    #pragma unroll
    for (int i = 0; i < 4; i++) { acc[i][0] = 0ull; acc[i][1] = 0ull; }

    #pragma unroll 4
    for (int k = 0; k < K; k++) {
        ulonglong2 wp = ((const ulonglong2*)(Ws + k * N))[nc];
        #pragma unroll
        for (int i = 0; i < 4; i++) {
            u64 xp = pack2(Xs[(rg * 4 + i) * XP + k]);
            ffma2(acc[i][0], xp, wp.x);
            ffma2(acc[i][1], xp, wp.y);
        }
    }

    #pragma unroll
    for (int i = 0; i < 4; i++) {
        int row = row0 + rg * 4 + i;
        if (row < M) {
            float dv = SCALE ? g_dinv[row] : 1.0f;
            float2 a = unpack2(acc[i][0]);
            float2 b = unpack2(acc[i][1]);
            float4 o = make_float4(a.x * dv, a.y * dv, b.x * dv, b.y * dv);
            ((float4*)C)[(size_t)row * (N / 4) + nc] = o;
        }
    }
}

// ---------- layer1 gather: agg1[v] = b1 + dinv[v]*(dinv[v]*h[v] + sum dinv[u]*h[u]) ----------
__global__ void gather128_kernel(const float* __restrict__ h,
                                 const float* __restrict__ bias,
                                 float* __restrict__ agg) {
    int gtid = blockIdx.x * blockDim.x + threadIdx.x;
    int v    = gtid >> 5;
    int lane = threadIdx.x & 31;
    if (v >= N_NODES) return;
    int rs = 0, re = 0; float dv = 0.f;
    if (lane == 0) {
        rs = g_rowstart[v];
        re = g_rowstart[v + 1];
        dv = g_dinv[v];
    }
    rs = __shfl_sync(0xffffffffu, rs, 0);
    re = __shfl_sync(0xffffffffu, re, 0);
    dv = __shfl_sync(0xffffffffu, dv, 0);

    const float4* h4 = (const float4*)h;
    float4 s = h4[(size_t)v * 32 + lane];   // self loop: dinv[v]*h[v]
    float4 acc = make_float4(s.x * dv, s.y * dv, s.z * dv, s.w * dv);
    int i = rs;
    for (; i + 4 <= re; i += 4) {
        int u0 = g_adj[i],     u1 = g_adj[i + 1];
        int u2 = g_adj[i + 2], u3 = g_adj[i + 3];
        float d0 = g_dinv[u0], d1 = g_dinv[u1];
        float d2 = g_dinv[u2], d3 = g_dinv[u3];
        float4 a = h4[(size_t)u0 * 32 + lane];
        float4 b = h4[(size_t)u1 * 32 + lane];
        float4 c = h4[(size_t)u2 * 32 + lane];
        float4 d = h4[(size_t)u3 * 32 + lane];
        acc.x += (a.x * d0 + b.x * d1) + (c.x * d2 + d.x * d3);
        acc.y += (a.y * d0 + b.y * d1) + (c.y * d2 + d.y * d3);
        acc.z += (a.z * d0 + b.z * d1) + (c.z * d2 + d.z * d3);
        acc.w += (a.w * d0 + b.w * d1) + (c.w * d2 + d.w * d3);
    }
    for (; i < re; i++) {
        int u = g_adj[i];
        float du = g_dinv[u];
        float4 a = h4[(size_t)u * 32 + lane];
        acc.x += a.x * du; acc.y += a.y * du;
        acc.z += a.z * du; acc.w += a.w * du;
    }
    float4 bb = ((const float4*)bias)[lane];
    float4 o = make_float4(bb.x + dv * acc.x, bb.y + dv * acc.y,
                           bb.z + dv * acc.z, bb.w + dv * acc.w);
    ((float4*)agg)[(size_t)v * 32 + lane] = o;
}

__device__ __forceinline__ void red_add_v4(float* p, float4 v) {
    asm volatile("red.global.add.v4.f32 [%0], {%1,%2,%3,%4};"
                 :: "l"(p), "f"(v.x), "f"(v.y), "f"(v.z), "f"(v.w)
                 : "memory");
}

// ---------------- layer2 gather + pool (hs2 pre-scaled by dinv) ----------------
__global__ void gather64_pool_kernel(const float* __restrict__ hs,
                                     const float* __restrict__ bias) {
    int gtid = blockIdx.x * blockDim.x + threadIdx.x;
    int v    = gtid >> 4;
    int sub  = threadIdx.x & 15;
    if (v >= N_NODES) return;
    int rs = 0, re = 0, g = 0; float dv = 0.f;
    if (sub == 0) {
        rs = g_rowstart[v];
        re = g_rowstart[v + 1];
        dv = g_dinv[v];
        g  = g_batch[v];
    }
    rs = __shfl_sync(0xffffffffu, rs, 0, 16);
    re = __shfl_sync(0xffffffffu, re, 0, 16);
    dv = __shfl_sync(0xffffffffu, dv, 0, 16);
    g  = __shfl_sync(0xffffffffu, g, 0, 16);

    const float4* hs4 = (const float4*)hs;
    float4 acc = hs4[(size_t)v * 16 + sub];    // self loop
    int i = rs;
    for (; i + 4 <= re; i += 4) {
        int u0 = g_adj[i],     u1 = g_adj[i + 1];
        int u2 = g_adj[i + 2], u3 = g_adj[i + 3];
        float4 a = hs4[(size_t)u0 * 16 + sub];
        float4 b = hs4[(size_t)u1 * 16 + sub];
        float4 c = hs4[(size_t)u2 * 16 + sub];
        float4 d = hs4[(size_t)u3 * 16 + sub];
        acc.x += (a.x + b.x) + (c.x + d.x);
        acc.y += (a.y + b.y) + (c.y + d.y);
        acc.z += (a.z + b.z) + (c.z + d.z);
        acc.w += (a.w + b.w) + (c.w + d.w);
    }
    for (; i < re; i++) {
        int u = g_adj[i];
        float4 a = hs4[(size_t)u * 16 + sub];
        acc.x += a.x; acc.y += a.y; acc.z += a.z; acc.w += a.w;
    }
    float4 bb = ((const float4*)bias)[sub];
    float4 o = make_float4(bb.x + dv * acc.x, bb.y + dv * acc.y,
                           bb.z + dv * acc.z, bb.w + dv * acc.w);
    red_add_v4(g_pool + (size_t)g * 64 + sub * 4, o);
}

// ---------------- final: out = (pool / max(cnt,1)) @ Wl + bl ----------------
__global__ void final_kernel(const float* __restrict__ Wl,
                             const float* __restrict__ bl,
                             float* __restrict__ out) {
    int g = blockIdx.x;
    int n = threadIdx.x;
    __shared__ float ps[64];
    float inv = 1.0f / fmaxf(g_cnt[g], 1.0f);
    ps[n] = g_pool[g * 64 + n] * inv;
    __syncthreads();
    float acc = bl[n];
    #pragma unroll
    for (int k = 0; k < 64; k++) acc += ps[k] * Wl[k * 64 + n];
    out[g * 64 + n] = acc;
}

// ---------------- launch ----------------
extern "C" void kernel_launch(void* const* d_in, const int* in_sizes, int n_in,
                              void* d_out, int out_size) {
    const float* x    = (const float*)d_in[0];
    const int*   ei32 = (const int*)d_in[1];
    const int*   b32  = (const int*)d_in[2];
    const float* W1   = (const float*)d_in[3];
    const float* b1   = (const float*)d_in[4];
    const float* W2   = (const float*)d_in[5];
    const float* b2   = (const float*)d_in[6];
    const float* Wl   = (const float*)d_in[7];
    const float* bl   = (const float*)d_in[8];
    float* out = (float*)d_out;

    float *p_h1, *p_agg1, *p_hs2;
    cudaGetSymbolAddress((void**)&p_h1,   g_h1);
    cudaGetSymbolAddress((void**)&p_agg1, g_agg1);
    cudaGetSymbolAddress((void**)&p_hs2,  g_hs2);

    const int SM_G1 = (128 * 128 + 32 * 132) * 4;   // 82432
    const int SM_G2 = (128 * 64 + 64 * 132) * 4;    // 66560
    cudaFuncSetAttribute((const void*)gemm_kernel<128, 32, false, false>,
                         cudaFuncAttributeMaxDynamicSharedMemorySize, SM_G1);
    cudaFuncSetAttribute((const void*)gemm_kernel<64, 64, true, true>,
                         cudaFuncAttributeMaxDynamicSharedMemorySize, SM_G2);

    // ---- fork: GEMM1 (independent of graph structure) on side stream ----
    cudaEventRecord(s_ev_fork, 0);
    cudaStreamWaitEvent(s_side, s_ev_fork, 0);
    gemm_kernel<128, 32, false, false>
        <<<(N_NODES + 31) / 32, 256, SM_G1, s_side>>>(x, W1, p_h1, N_NODES);
    cudaEventRecord(s_ev_gemm1, s_side);

    // ---- main stream: CSR build ----
    detect_zero_kernel<<<NBLK, 256>>>(ei32, b32);
    convert_kernel<<<(N_EDGES + 255) / 256, 256>>>(ei32, b32);
    scanA_kernel<<<NBLK, 256>>>();
    scanC_kernel<<<NBLK, 256>>>();
    scatter_kernel<<<(N_EDGES + 255) / 256, 256>>>();

    // ---- join: gather needs both CSR and h1 ----
    cudaStreamWaitEvent(0, s_ev_gemm1, 0);
    gather128_kernel<<<(N_NODES * 32 + 255) / 256, 256>>>(p_h1, b1, p_agg1);

    // layer 2 (+ fused pool)
    gemm_kernel<64, 64, true, true>
        <<<(N_NODES + 63) / 64, 256, SM_G2>>>(p_agg1, W2, p_hs2, N_NODES);
    gather64_pool_kernel<<<(N_NODES * 16 + 255) / 256, 256>>>(p_hs2, b2);

    // final linear
    final_kernel<<<NUM_GRAPHS, 64>>>(Wl, bl, out);
}

// round 5
// speedup vs baseline: 1.7903x; 1.1004x over previous
#include <cuda_runtime.h>
#include <cuda_fp16.h>

#define N_NODES   50000
#define N_EDGES   800000
#define NUM_GRAPHS 512
#define F1 128
#define F2 64
#define NBLK 196   // ceil(N_NODES/256)

typedef unsigned long long u64;

// ---------------- scratch (device globals: allocation-free) ----------------
__device__ int    g_degi[N_NODES];
__device__ int    g_rowstart[N_NODES + 1];
__device__ int    g_cursor[N_NODES];
__device__ int    g_adj[N_EDGES];
__device__ int    g_blocksum[NBLK];
__device__ float  g_dinv[N_NODES];
__device__ __half g_h1[(size_t)N_NODES * F1];    // x@W1 (unscaled, fp16)
__device__ float  g_agg1[(size_t)N_NODES * F1];
__device__ __half g_hs2[(size_t)N_NODES * F2];   // dinv * (relu(agg1)@W2), fp16
__device__ float  g_pool[NUM_GRAPHS * F2];
__device__ float  g_cnt[NUM_GRAPHS];
__device__ int    g_src[N_EDGES];
__device__ int    g_dst[N_EDGES];
__device__ int    g_batch[N_NODES];
__device__ int    g_is64_edge;
__device__ int    g_is64_batch;

// ---------------- static side stream + events ----------------
static cudaStream_t s_side;
static cudaEvent_t  s_ev_fork, s_ev_gemm1;
namespace {
struct StreamInit {
    StreamInit() {
        cudaStreamCreateWithFlags(&s_side, cudaStreamNonBlocking);
        cudaEventCreateWithFlags(&s_ev_fork,  cudaEventDisableTiming);
        cudaEventCreateWithFlags(&s_ev_gemm1, cudaEventDisableTiming);
    }
};
static StreamInit s_stream_init;
}

// ---------------- f32x2 helpers ----------------
__device__ __forceinline__ u64 pack2(float x) {
    u64 r; asm("mov.b64 %0, {%1, %1};" : "=l"(r) : "f"(x)); return r;
}
__device__ __forceinline__ void ffma2(u64& d, u64 a, u64 b) {
    asm("fma.rn.f32x2 %0, %1, %2, %0;" : "+l"(d) : "l"(a), "l"(b));
}
__device__ __forceinline__ float2 unpack2(u64 v) {
    float2 r; asm("mov.b64 {%0, %1}, %2;" : "=f"(r.x), "=f"(r.y) : "l"(v)); return r;
}
// uint2 (4 halves) -> 4 floats
__device__ __forceinline__ float4 h4_to_f4(uint2 w) {
    __half2 lo = *reinterpret_cast<__half2*>(&w.x);
    __half2 hi = *reinterpret_cast<__half2*>(&w.y);
    float2 a = __half22float2(lo);
    float2 b = __half22float2(hi);
    return make_float4(a.x, a.y, b.x, b.y);
}

// ---------------- detect dtype + zero scratch ----------------
__global__ void detect_zero_kernel(const int* __restrict__ ei32,
                                   const int* __restrict__ b32) {
    int i = blockIdx.x * blockDim.x + threadIdx.x;
    if (i < N_NODES)          g_degi[i] = 0;
    if (i < NUM_GRAPHS * F2)  g_pool[i] = 0.0f;
    if (i < NUM_GRAPHS)       g_cnt[i]  = 0.0f;

    if (blockIdx.x == 0) {
        __shared__ int s_e, s_b;
        if (threadIdx.x == 0) { s_e = 0; s_b = 0; }
        __syncthreads();
        int t = threadIdx.x;
        long long ie = (long long)t * 3121 + 5;
        if (ei32[2 * ie + 1] != 0) atomicOr(&s_e, 1);
        long long ib = N_NODES / 2 - 1 - t;
        if (b32[2 * ib + 1] != 0) atomicOr(&s_b, 1);
        __syncthreads();
        if (threadIdx.x == 0) {
            g_is64_edge  = s_e ? 0 : 1;
            g_is64_batch = s_b ? 0 : 1;
        }
    }
}

// ---------------- convert indices, count degrees, count graph sizes ----------------
__global__ void convert_kernel(const int* __restrict__ ei32,
                               const int* __restrict__ b32) {
    int i = blockIdx.x * blockDim.x + threadIdx.x;
    int e64 = g_is64_edge, b64 = g_is64_batch;
    if (i < N_EDGES) {
        int s = e64 ? ei32[2 * (size_t)i]             : ei32[i];
        int d = e64 ? ei32[2 * ((size_t)N_EDGES + i)] : ei32[N_EDGES + i];
        g_src[i] = s;
        g_dst[i] = d;
        atomicAdd(&g_degi[d], 1);
    }
    if (i < N_NODES) {
        int b = b64 ? b32[2 * (size_t)i] : b32[i];
        g_batch[i] = b;
        atomicAdd(&g_cnt[b], 1.0f);
    }
}

// ---------------- 2-phase coalesced exclusive scan ----------------
__global__ void scanA_kernel() {
    __shared__ int sh[256];
    int idx = blockIdx.x * 256 + threadIdx.x;
    int d = (idx < N_NODES) ? g_degi[idx] : 0;
    sh[threadIdx.x] = d;
    __syncthreads();
    #pragma unroll
    for (int off = 128; off > 0; off >>= 1) {
        if (threadIdx.x < off) sh[threadIdx.x] += sh[threadIdx.x + off];
        __syncthreads();
    }
    if (threadIdx.x == 0) g_blocksum[blockIdx.x] = sh[0];
}

__global__ void scanC_kernel() {
    __shared__ int soff[256];
    __shared__ int sh[256];
    int t = threadIdx.x;
    int bs = (t < NBLK && t < blockIdx.x) ? g_blocksum[t] : 0;
    soff[t] = bs;
    __syncthreads();
    #pragma unroll
    for (int off = 128; off > 0; off >>= 1) {
        if (t < off) soff[t] += soff[t + off];
        __syncthreads();
    }
    int blockoff = soff[0];

    int idx = blockIdx.x * 256 + t;
    int d = (idx < N_NODES) ? g_degi[idx] : 0;
    sh[t] = d;
    __syncthreads();
    #pragma unroll
    for (int off = 1; off < 256; off <<= 1) {
        int u = (t >= off) ? sh[t - off] : 0;
        __syncthreads();
        sh[t] += u;
        __syncthreads();
    }
    if (idx < N_NODES) {
        int excl = blockoff + sh[t] - d;
        g_rowstart[idx] = excl;
        g_cursor[idx]   = excl;
        g_dinv[idx]     = rsqrtf((float)(d + 1));
        if (idx == N_NODES - 1) g_rowstart[N_NODES] = N_EDGES;
    }
}

__global__ void scatter_kernel() {
    int i = blockIdx.x * blockDim.x + threadIdx.x;
    if (i >= N_EDGES) return;
    int pos = atomicAdd(&g_cursor[g_dst[i]], 1);
    g_adj[pos] = g_src[i];
}

// ---------------- GEMM: out = [dinv *] op(A[M,128]) @ W[128,N], fp16 output ----------------
template <int N, int BM, bool RELU, bool SCALE>
__global__ void gemm_kernel(const float* __restrict__ A,
                            const float* __restrict__ W,
                            __half* __restrict__ C, int M) {
    constexpr int K  = 128;
    constexpr int XP = K + 4;
    constexpr int NT = (N / 4) * (BM / 4);
    extern __shared__ float sm[];
    float* Ws = sm;                  // K*N
    float* Xs = sm + K * N;          // BM*XP

    int tid = threadIdx.x;
    const float4* W4 = (const float4*)W;
    float4* Ws4w = (float4*)Ws;
    #pragma unroll
    for (int idx = tid; idx < K * N / 4; idx += NT) Ws4w[idx] = W4[idx];

    int row0 = blockIdx.x * BM;
    for (int idx = tid; idx < BM * 32; idx += NT) {
        int r  = idx >> 5;
        int k4 = idx & 31;
        int row = row0 + r;
        float4 v = make_float4(0.f, 0.f, 0.f, 0.f);
        if (row < M) v = ((const float4*)A)[(size_t)row * 32 + k4];
        if (RELU) {
            v.x = fmaxf(v.x, 0.f); v.y = fmaxf(v.y, 0.f);
            v.z = fmaxf(v.z, 0.f); v.w = fmaxf(v.w, 0.f);
        }
        *(float4*)&Xs[r * XP + k4 * 4] = v;
    }
    __syncthreads();

    int nc = tid % (N / 4);
    int rg = tid / (N / 4);
    u64 acc[4][2];
    #pragma unroll
    for (int i = 0; i < 4; i++) { acc[i][0] = 0ull; acc[i][1] = 0ull; }

    #pragma unroll 4
    for (int k = 0; k < K; k++) {
        ulonglong2 wp = ((const ulonglong2*)(Ws + k * N))[nc];
        #pragma unroll
        for (int i = 0; i < 4; i++) {
            u64 xp = pack2(Xs[(rg * 4 + i) * XP + k]);
            ffma2(acc[i][0], xp, wp.x);
            ffma2(acc[i][1], xp, wp.y);
        }
    }

    #pragma unroll
    for (int i = 0; i < 4; i++) {
        int row = row0 + rg * 4 + i;
        if (row < M) {
            float dv = SCALE ? g_dinv[row] : 1.0f;
            float2 a = unpack2(acc[i][0]);
            float2 b = unpack2(acc[i][1]);
            __half2 p0 = __floats2half2_rn(a.x * dv, a.y * dv);
            __half2 p1 = __floats2half2_rn(b.x * dv, b.y * dv);
            uint2 o;
            o.x = *reinterpret_cast<unsigned*>(&p0);
            o.y = *reinterpret_cast<unsigned*>(&p1);
            ((uint2*)C)[(size_t)row * (N / 4) + nc] = o;   // N/4 uint2 per row
        }
    }
}

// ---------- layer1 gather (fp16 h): agg1[v] = b1 + dinv[v]*(dinv[v]*h[v] + sum dinv[u]*h[u]) ----------
__global__ void gather128_kernel(const __half* __restrict__ h,
                                 const float* __restrict__ bias,
                                 float* __restrict__ agg) {
    int gtid = blockIdx.x * blockDim.x + threadIdx.x;
    int v    = gtid >> 5;
    int lane = threadIdx.x & 31;
    if (v >= N_NODES) return;
    int rs = 0, re = 0; float dv = 0.f;
    if (lane == 0) {
        rs = g_rowstart[v];
        re = g_rowstart[v + 1];
        dv = g_dinv[v];
    }
    rs = __shfl_sync(0xffffffffu, rs, 0);
    re = __shfl_sync(0xffffffffu, re, 0);
    dv = __shfl_sync(0xffffffffu, dv, 0);

    const uint2* h2 = (const uint2*)h;   // 32 uint2 per row (128 halves)
    float4 s = h4_to_f4(h2[(size_t)v * 32 + lane]);
    float4 acc = make_float4(s.x * dv, s.y * dv, s.z * dv, s.w * dv);
    int i = rs;
    for (; i + 4 <= re; i += 4) {
        int u0 = g_adj[i],     u1 = g_adj[i + 1];
        int u2 = g_adj[i + 2], u3 = g_adj[i + 3];
        float d0 = g_dinv[u0], d1 = g_dinv[u1];
        float d2 = g_dinv[u2], d3 = g_dinv[u3];
        float4 a = h4_to_f4(h2[(size_t)u0 * 32 + lane]);
        float4 b = h4_to_f4(h2[(size_t)u1 * 32 + lane]);
        float4 c = h4_to_f4(h2[(size_t)u2 * 32 + lane]);
        float4 d = h4_to_f4(h2[(size_t)u3 * 32 + lane]);
        acc.x += (a.x * d0 + b.x * d1) + (c.x * d2 + d.x * d3);
        acc.y += (a.y * d0 + b.y * d1) + (c.y * d2 + d.y * d3);
        acc.z += (a.z * d0 + b.z * d1) + (c.z * d2 + d.z * d3);
        acc.w += (a.w * d0 + b.w * d1) + (c.w * d2 + d.w * d3);
    }
    for (; i < re; i++) {
        int u = g_adj[i];
        float du = g_dinv[u];
        float4 a = h4_to_f4(h2[(size_t)u * 32 + lane]);
        acc.x += a.x * du; acc.y += a.y * du;
        acc.z += a.z * du; acc.w += a.w * du;
    }
    float4 bb = ((const float4*)bias)[lane];
    float4 o = make_float4(bb.x + dv * acc.x, bb.y + dv * acc.y,
                           bb.z + dv * acc.z, bb.w + dv * acc.w);
    ((float4*)agg)[(size_t)v * 32 + lane] = o;
}

__device__ __forceinline__ void red_add_v4(float* p, float4 v) {
    asm volatile("red.global.add.v4.f32 [%0], {%1,%2,%3,%4};"
                 :: "l"(p), "f"(v.x), "f"(v.y), "f"(v.z), "f"(v.w)
                 : "memory");
}

// ---------------- layer2 gather + pool (fp16 hs2, pre-scaled by dinv) ----------------
__global__ void gather64_pool_kernel(const __half* __restrict__ hs,
                                     const float* __restrict__ bias) {
    int gtid = blockIdx.x * blockDim.x + threadIdx.x;
    int v    = gtid >> 4;
    int sub  = threadIdx.x & 15;
    if (v >= N_NODES) return;
    int rs = 0, re = 0, g = 0; float dv = 0.f;
    if (sub == 0) {
        rs = g_rowstart[v];
        re = g_rowstart[v + 1];
        dv = g_dinv[v];
        g  = g_batch[v];
    }
    rs = __shfl_sync(0xffffffffu, rs, 0, 16);
    re = __shfl_sync(0xffffffffu, re, 0, 16);
    dv = __shfl_sync(0xffffffffu, dv, 0, 16);
    g  = __shfl_sync(0xffffffffu, g, 0, 16);

    const uint2* hs2p = (const uint2*)hs;  // 16 uint2 per row (64 halves)
    float4 acc = h4_to_f4(hs2p[(size_t)v * 16 + sub]);   // self loop
    int i = rs;
    for (; i + 4 <= re; i += 4) {
        int u0 = g_adj[i],     u1 = g_adj[i + 1];
        int u2 = g_adj[i + 2], u3 = g_adj[i + 3];
        float4 a = h4_to_f4(hs2p[(size_t)u0 * 16 + sub]);
        float4 b = h4_to_f4(hs2p[(size_t)u1 * 16 + sub]);
        float4 c = h4_to_f4(hs2p[(size_t)u2 * 16 + sub]);
        float4 d = h4_to_f4(hs2p[(size_t)u3 * 16 + sub]);
        acc.x += (a.x + b.x) + (c.x + d.x);
        acc.y += (a.y + b.y) + (c.y + d.y);
        acc.z += (a.z + b.z) + (c.z + d.z);
        acc.w += (a.w + b.w) + (c.w + d.w);
    }
    for (; i < re; i++) {
        int u = g_adj[i];
        float4 a = h4_to_f4(hs2p[(size_t)u * 16 + sub]);
        acc.x += a.x; acc.y += a.y; acc.z += a.z; acc.w += a.w;
    }
    float4 bb = ((const float4*)bias)[sub];
    float4 o = make_float4(bb.x + dv * acc.x, bb.y + dv * acc.y,
                           bb.z + dv * acc.z, bb.w + dv * acc.w);
    red_add_v4(g_pool + (size_t)g * 64 + sub * 4, o);
}

// ---------------- final: out = (pool / max(cnt,1)) @ Wl + bl ----------------
__global__ void final_kernel(const float* __restrict__ Wl,
                             const float* __restrict__ bl,
                             float* __restrict__ out) {
    int g = blockIdx.x;
    int n = threadIdx.x;
    __shared__ float ps[64];
    float inv = 1.0f / fmaxf(g_cnt[g], 1.0f);
    ps[n] = g_pool[g * 64 + n] * inv;
    __syncthreads();
    float acc = bl[n];
    #pragma unroll
    for (int k = 0; k < 64; k++) acc += ps[k] * Wl[k * 64 + n];
    out[g * 64 + n] = acc;
}

// ---------------- launch ----------------
extern "C" void kernel_launch(void* const* d_in, const int* in_sizes, int n_in,
                              void* d_out, int out_size) {
    const float* x    = (const float*)d_in[0];
    const int*   ei32 = (const int*)d_in[1];
    const int*   b32  = (const int*)d_in[2];
    const float* W1   = (const float*)d_in[3];
    const float* b1   = (const float*)d_in[4];
    const float* W2   = (const float*)d_in[5];
    const float* b2   = (const float*)d_in[6];
    const float* Wl   = (const float*)d_in[7];
    const float* bl   = (const float*)d_in[8];
    float* out = (float*)d_out;

    __half *p_h1, *p_hs2;
    float  *p_agg1;
    cudaGetSymbolAddress((void**)&p_h1,   g_h1);
    cudaGetSymbolAddress((void**)&p_agg1, g_agg1);
    cudaGetSymbolAddress((void**)&p_hs2,  g_hs2);

    const int SM_G1 = (128 * 128 + 32 * 132) * 4;   // 82432
    const int SM_G2 = (128 * 64 + 64 * 132) * 4;    // 66560
    cudaFuncSetAttribute((const void*)gemm_kernel<128, 32, false, false>,
                         cudaFuncAttributeMaxDynamicSharedMemorySize, SM_G1);
    cudaFuncSetAttribute((const void*)gemm_kernel<64, 64, true, true>,
                         cudaFuncAttributeMaxDynamicSharedMemorySize, SM_G2);

    // ---- fork: GEMM1 on side stream ----
    cudaEventRecord(s_ev_fork, 0);
    cudaStreamWaitEvent(s_side, s_ev_fork, 0);
    gemm_kernel<128, 32, false, false>
        <<<(N_NODES + 31) / 32, 256, SM_G1, s_side>>>(x, W1, p_h1, N_NODES);
    cudaEventRecord(s_ev_gemm1, s_side);

    // ---- main stream: CSR build ----
    detect_zero_kernel<<<NBLK, 256>>>(ei32, b32);
    convert_kernel<<<(N_EDGES + 255) / 256, 256>>>(ei32, b32);
    scanA_kernel<<<NBLK, 256>>>();
    scanC_kernel<<<NBLK, 256>>>();
    scatter_kernel<<<(N_EDGES + 255) / 256, 256>>>();

    // ---- join ----
    cudaStreamWaitEvent(0, s_ev_gemm1, 0);
    gather128_kernel<<<(N_NODES * 32 + 255) / 256, 256>>>(p_h1, b1, p_agg1);

    // layer 2 (+ fused pool)
    gemm_kernel<64, 64, true, true>
        <<<(N_NODES + 63) / 64, 256, SM_G2>>>(p_agg1, W2, p_hs2, N_NODES);
    gather64_pool_kernel<<<(N_NODES * 16 + 255) / 256, 256>>>(p_hs2, b2);

    // final linear
    final_kernel<<<NUM_GRAPHS, 64>>>(Wl, bl, out);
}

// round 6
// speedup vs baseline: 2.7198x; 1.5192x over previous
#include <cuda_runtime.h>
#include <cuda_fp16.h>

#define N_NODES   50000
#define N_EDGES   800000
#define NUM_GRAPHS 512
#define F1 128
#define F2 64
#define NBLK 196   // ceil(N_NODES/256)

// ---------------- scratch (device globals: allocation-free) ----------------
__device__ int    g_degi[N_NODES];
__device__ int    g_rowstart[N_NODES + 1];
__device__ int    g_cursor[N_NODES];
__device__ int    g_adj[N_EDGES];
__device__ int    g_blocksum[NBLK];
__device__ float  g_dinv[N_NODES];
__device__ __half g_w1t[128 * 128];              // W1^T fp16 [n][k]
__device__ __half g_w2t[64 * 128];               // W2^T fp16 [n][k]
__device__ __half g_h1[(size_t)N_NODES * F1];    // x@W1 (fp16)
__device__ __half g_agg1[(size_t)N_NODES * F1];  // relu(gcn1) (fp16)
__device__ __half g_hs2[(size_t)N_NODES * F2];   // dinv * (relu(agg1)@W2) (fp16)
__device__ float  g_pool[NUM_GRAPHS * F2];
__device__ float  g_cnt[NUM_GRAPHS];
__device__ int    g_src[N_EDGES];
__device__ int    g_dst[N_EDGES];
__device__ int    g_batch[N_NODES];
__device__ int    g_is64_edge;
__device__ int    g_is64_batch;

// ---------------- static side stream + events ----------------
static cudaStream_t s_side;
static cudaEvent_t  s_ev_fork, s_ev_gemm1;
namespace {
struct StreamInit {
    StreamInit() {
        cudaStreamCreateWithFlags(&s_side, cudaStreamNonBlocking);
        cudaEventCreateWithFlags(&s_ev_fork,  cudaEventDisableTiming);
        cudaEventCreateWithFlags(&s_ev_gemm1, cudaEventDisableTiming);
    }
};
static StreamInit s_stream_init;
}

// ---------------- helpers ----------------
__device__ __forceinline__ float4 h4_to_f4(uint2 w) {
    __half2 lo = *reinterpret_cast<__half2*>(&w.x);
    __half2 hi = *reinterpret_cast<__half2*>(&w.y);
    float2 a = __half22float2(lo);
    float2 b = __half22float2(hi);
    return make_float4(a.x, a.y, b.x, b.y);
}
__device__ __forceinline__ unsigned h2bits(__half2 h) {
    return *reinterpret_cast<unsigned*>(&h);
}

// ---------------- detect dtype + zero scratch ----------------
__global__ void detect_zero_kernel(const int* __restrict__ ei32,
                                   const int* __restrict__ b32) {
    int i = blockIdx.x * blockDim.x + threadIdx.x;
    if (i < N_NODES)          g_degi[i] = 0;
    if (i < NUM_GRAPHS * F2)  g_pool[i] = 0.0f;
    if (i < NUM_GRAPHS)       g_cnt[i]  = 0.0f;

    if (blockIdx.x == 0) {
        __shared__ int s_e, s_b;
        if (threadIdx.x == 0) { s_e = 0; s_b = 0; }
        __syncthreads();
        int t = threadIdx.x;
        long long ie = (long long)t * 3121 + 5;
        if (ei32[2 * ie + 1] != 0) atomicOr(&s_e, 1);
        long long ib = N_NODES / 2 - 1 - t;
        if (b32[2 * ib + 1] != 0) atomicOr(&s_b, 1);
        __syncthreads();
        if (threadIdx.x == 0) {
            g_is64_edge  = s_e ? 0 : 1;
            g_is64_batch = s_b ? 0 : 1;
        }
    }
}

// ---------------- prep: transpose + fp16-convert weights ----------------
__global__ void prep_w_kernel(const float* __restrict__ W1,
                              const float* __restrict__ W2) {
    int i = blockIdx.x * 256 + threadIdx.x;
    if (i < 128 * 128) {
        int n = i >> 7, k = i & 127;
        g_w1t[i] = __float2half(W1[k * 128 + n]);
    }
    if (i < 64 * 128) {
        int n = i >> 7, k = i & 127;
        g_w2t[i] = __float2half(W2[k * 64 + n]);
    }
}

// ---------------- convert indices, count degrees, count graph sizes ----------------
__global__ void convert_kernel(const int* __restrict__ ei32,
                               const int* __restrict__ b32) {
    int i = blockIdx.x * blockDim.x + threadIdx.x;
    int e64 = g_is64_edge, b64 = g_is64_batch;
    if (i < N_EDGES) {
        int s = e64 ? ei32[2 * (size_t)i]             : ei32[i];
        int d = e64 ? ei32[2 * ((size_t)N_EDGES + i)] : ei32[N_EDGES + i];
        g_src[i] = s;
        g_dst[i] = d;
        atomicAdd(&g_degi[d], 1);
    }
    if (i < N_NODES) {
        int b = b64 ? b32[2 * (size_t)i] : b32[i];
        g_batch[i] = b;
        atomicAdd(&g_cnt[b], 1.0f);
    }
}

// ---------------- 2-phase coalesced exclusive scan ----------------
__global__ void scanA_kernel() {
    __shared__ int sh[256];
    int idx = blockIdx.x * 256 + threadIdx.x;
    int d = (idx < N_NODES) ? g_degi[idx] : 0;
    sh[threadIdx.x] = d;
    __syncthreads();
    #pragma unroll
    for (int off = 128; off > 0; off >>= 1) {
        if (threadIdx.x < off) sh[threadIdx.x] += sh[threadIdx.x + off];
        __syncthreads();
    }
    if (threadIdx.x == 0) g_blocksum[blockIdx.x] = sh[0];
}

__global__ void scanC_kernel() {
    __shared__ int soff[256];
    __shared__ int sh[256];
    int t = threadIdx.x;
    int bs = (t < NBLK && t < blockIdx.x) ? g_blocksum[t] : 0;
    soff[t] = bs;
    __syncthreads();
    #pragma unroll
    for (int off = 128; off > 0; off >>= 1) {
        if (t < off) soff[t] += soff[t + off];
        __syncthreads();
    }
    int blockoff = soff[0];

    int idx = blockIdx.x * 256 + t;
    int d = (idx < N_NODES) ? g_degi[idx] : 0;
    sh[t] = d;
    __syncthreads();
    #pragma unroll
    for (int off = 1; off < 256; off <<= 1) {
        int u = (t >= off) ? sh[t - off] : 0;
        __syncthreads();
        sh[t] += u;
        __syncthreads();
    }
    if (idx < N_NODES) {
        int excl = blockoff + sh[t] - d;
        g_rowstart[idx] = excl;
        g_cursor[idx]   = excl;
        g_dinv[idx]     = rsqrtf((float)(d + 1));
        if (idx == N_NODES - 1) g_rowstart[N_NODES] = N_EDGES;
    }
}

__global__ void scatter_kernel() {
    int i = blockIdx.x * blockDim.x + threadIdx.x;
    if (i >= N_EDGES) return;
    int pos = atomicAdd(&g_cursor[g_dst[i]], 1);
    g_adj[pos] = g_src[i];
}

// ---------------- tensor-core GEMM: C = [dinv *] A[M,128] @ Wt^T, fp16 out ----------------
// mma.sync.m16n8k16 row.col f32.f16.f16.f32. Block: 64 rows x N cols, 8 warps
// (4 row-groups x 2 col-groups of WC columns). Smem row stride 136 halves
// (conflict-free quad access: word = 68*row + k/2, 68 mod 32 = 4).
template <int N, int WC, bool A_HALF, bool SCALE>
__global__ void mma_gemm_kernel(const void* __restrict__ Ain,
                                const __half* __restrict__ Wt,
                                __half* __restrict__ C, int M) {
    constexpr int NT  = WC / 8;
    constexpr int STR = 136;
    extern __shared__ __half sh[];
    __half* Asm = sh;              // 64 x STR
    __half* Bsm = sh + 64 * STR;   // N x STR

    int tid  = threadIdx.x;
    int row0 = blockIdx.x * 64;

    // fill B from Wt [N][128] fp16 (coalesced 16B)
    const uint4* Wt4 = (const uint4*)Wt;
    #pragma unroll
    for (int idx = tid; idx < N * 16; idx += 256) {
        int n = idx >> 4, kc = idx & 15;
        *(uint4*)(Bsm + n * STR + kc * 8) = Wt4[idx];
    }
    // fill A (64 rows x 128 k)
    if (A_HALF) {
        const uint2* A2 = (const uint2*)Ain;
        #pragma unroll
        for (int idx = tid; idx < 64 * 32; idx += 256) {
            int r = idx >> 5, c4 = idx & 31;
            int row = row0 + r;
            uint2 v = make_uint2(0u, 0u);
            if (row < M) v = A2[(size_t)row * 32 + c4];
            *(uint2*)(Asm + r * STR + c4 * 4) = v;
        }
    } else {
        const float4* A4 = (const float4*)Ain;
        #pragma unroll
        for (int idx = tid; idx < 64 * 32; idx += 256) {
            int r = idx >> 5, c4 = idx & 31;
            int row = row0 + r;
            float4 v = make_float4(0.f, 0.f, 0.f, 0.f);
            if (row < M) v = A4[(size_t)row * 32 + c4];
            uint2 o;
            o.x = h2bits(__floats2half2_rn(v.x, v.y));
            o.y = h2bits(__floats2half2_rn(v.z, v.w));
            *(uint2*)(Asm + r * STR + c4 * 4) = o;
        }
    }
    __syncthreads();

    int lane = tid & 31, warp = tid >> 5;
    int wr = warp >> 1, wc = warp & 1;
    int gid = lane >> 2, q = lane & 3;

    float c[NT][4];
    #pragma unroll
    for (int j = 0; j < NT; j++) {
        c[j][0] = 0.f; c[j][1] = 0.f; c[j][2] = 0.f; c[j][3] = 0.f;
    }

    const __half* Abase = Asm + (wr * 16 + gid) * STR;
    #pragma unroll
    for (int s = 0; s < 8; s++) {
        int k0 = s * 16 + q * 2;
        unsigned a0 = *(const unsigned*)(Abase + k0);
        unsigned a1 = *(const unsigned*)(Abase + 8 * STR + k0);
        unsigned a2 = *(const unsigned*)(Abase + k0 + 8);
        unsigned a3 = *(const unsigned*)(Abase + 8 * STR + k0 + 8);
        #pragma unroll
        for (int j = 0; j < NT; j++) {
            const __half* Bp = Bsm + (wc * WC + j * 8 + gid) * STR + k0;
            unsigned b0 = *(const unsigned*)(Bp);
            unsigned b1 = *(const unsigned*)(Bp + 8);
            asm volatile(
                "mma.sync.aligned.m16n8k16.row.col.f32.f16.f16.f32 "
                "{%0,%1,%2,%3}, {%4,%5,%6,%7}, {%8,%9}, {%0,%1,%2,%3};"
                : "+f"(c[j][0]), "+f"(c[j][1]), "+f"(c[j][2]), "+f"(c[j][3])
                : "r"(a0), "r"(a1), "r"(a2), "r"(a3), "r"(b0), "r"(b1));
        }
    }

    int ra = row0 + wr * 16 + gid;
    int rb = ra + 8;
    float dva = 1.f, dvb = 1.f;
    if (SCALE) {
        if (ra < M) dva = g_dinv[ra];
        if (rb < M) dvb = g_dinv[rb];
    }
    #pragma unroll
    for (int j = 0; j < NT; j++) {
        int n = wc * WC + j * 8 + q * 2;
        if (ra < M)
            *(__half2*)(C + (size_t)ra * N + n) =
                __floats2half2_rn(c[j][0] * dva, c[j][1] * dva);
        if (rb < M)
            *(__half2*)(C + (size_t)rb * N + n) =
                __floats2half2_rn(c[j][2] * dvb, c[j][3] * dvb);
    }
}

// ---------- layer1 gather + relu: agg1[v] = relu(b1 + dinv[v]*(dinv[v]*h[v] + sum dinv[u]*h[u])) ----------
__global__ void gather128_kernel(const __half* __restrict__ h,
                                 const float* __restrict__ bias,
                                 __half* __restrict__ agg) {
    int gtid = blockIdx.x * blockDim.x + threadIdx.x;
    int v    = gtid >> 5;
    int lane = threadIdx.x & 31;
    if (v >= N_NODES) return;
    int rs = 0, re = 0; float dv = 0.f;
    if (lane == 0) {
        rs = g_rowstart[v];
        re = g_rowstart[v + 1];
        dv = g_dinv[v];
    }
    rs = __shfl_sync(0xffffffffu, rs, 0);
    re = __shfl_sync(0xffffffffu, re, 0);
    dv = __shfl_sync(0xffffffffu, dv, 0);

    const uint2* h2 = (const uint2*)h;   // 32 uint2 per row (128 halves)
    float4 s = h4_to_f4(h2[(size_t)v * 32 + lane]);
    float4 acc = make_float4(s.x * dv, s.y * dv, s.z * dv, s.w * dv);
    int i = rs;
    for (; i + 4 <= re; i += 4) {
        int u0 = g_adj[i],     u1 = g_adj[i + 1];
        int u2 = g_adj[i + 2], u3 = g_adj[i + 3];
        float d0 = g_dinv[u0], d1 = g_dinv[u1];
        float d2 = g_dinv[u2], d3 = g_dinv[u3];
        float4 a = h4_to_f4(h2[(size_t)u0 * 32 + lane]);
        float4 b = h4_to_f4(h2[(size_t)u1 * 32 + lane]);
        float4 cc = h4_to_f4(h2[(size_t)u2 * 32 + lane]);
        float4 d = h4_to_f4(h2[(size_t)u3 * 32 + lane]);
        acc.x += (a.x * d0 + b.x * d1) + (cc.x * d2 + d.x * d3);
        acc.y += (a.y * d0 + b.y * d1) + (cc.y * d2 + d.y * d3);
        acc.z += (a.z * d0 + b.z * d1) + (cc.z * d2 + d.z * d3);
        acc.w += (a.w * d0 + b.w * d1) + (cc.w * d2 + d.w * d3);
    }
    for (; i < re; i++) {
        int u = g_adj[i];
        float du = g_dinv[u];
        float4 a = h4_to_f4(h2[(size_t)u * 32 + lane]);
        acc.x += a.x * du; acc.y += a.y * du;
        acc.z += a.z * du; acc.w += a.w * du;
    }
    float4 bb = ((const float4*)bias)[lane];
    float ox = fmaxf(bb.x + dv * acc.x, 0.f);
    float oy = fmaxf(bb.y + dv * acc.y, 0.f);
    float oz = fmaxf(bb.z + dv * acc.z, 0.f);
    float ow = fmaxf(bb.w + dv * acc.w, 0.f);
    uint2 st;
    st.x = h2bits(__floats2half2_rn(ox, oy));
    st.y = h2bits(__floats2half2_rn(oz, ow));
    ((uint2*)agg)[(size_t)v * 32 + lane] = st;
}

__device__ __forceinline__ void red_add_v4(float* p, float4 v) {
    asm volatile("red.global.add.v4.f32 [%0], {%1,%2,%3,%4};"
                 :: "l"(p), "f"(v.x), "f"(v.y), "f"(v.z), "f"(v.w)
                 : "memory");
}

// ---------------- layer2 gather + pool (fp16 hs2, pre-scaled by dinv) ----------------
__global__ void gather64_pool_kernel(const __half* __restrict__ hs,
                                     const float* __restrict__ bias) {
    int gtid = blockIdx.x * blockDim.x + threadIdx.x;
    int v    = gtid >> 4;
    int sub  = threadIdx.x & 15;
    if (v >= N_NODES) return;
    int rs = 0, re = 0, g = 0; float dv = 0.f;
    if (sub == 0) {
        rs = g_rowstart[v];
        re = g_rowstart[v + 1];
        dv = g_dinv[v];
        g  = g_batch[v];
    }
    rs = __shfl_sync(0xffffffffu, rs, 0, 16);
    re = __shfl_sync(0xffffffffu, re, 0, 16);
    dv = __shfl_sync(0xffffffffu, dv, 0, 16);
    g  = __shfl_sync(0xffffffffu, g, 0, 16);

    const uint2* hs2p = (const uint2*)hs;  // 16 uint2 per row (64 halves)
    float4 acc = h4_to_f4(hs2p[(size_t)v * 16 + sub]);   // self loop
    int i = rs;
    for (; i + 4 <= re; i += 4) {
        int u0 = g_adj[i],     u1 = g_adj[i + 1];
        int u2 = g_adj[i + 2], u3 = g_adj[i + 3];
        float4 a = h4_to_f4(hs2p[(size_t)u0 * 16 + sub]);
        float4 b = h4_to_f4(hs2p[(size_t)u1 * 16 + sub]);
        float4 c = h4_to_f4(hs2p[(size_t)u2 * 16 + sub]);
        float4 d = h4_to_f4(hs2p[(size_t)u3 * 16 + sub]);
        acc.x += (a.x + b.x) + (c.x + d.x);
        acc.y += (a.y + b.y) + (c.y + d.y);
        acc.z += (a.z + b.z) + (c.z + d.z);
        acc.w += (a.w + b.w) + (c.w + d.w);
    }
    for (; i < re; i++) {
        int u = g_adj[i];
        float4 a = h4_to_f4(hs2p[(size_t)u * 16 + sub]);
        acc.x += a.x; acc.y += a.y; acc.z += a.z; acc.w += a.w;
    }
    float4 bb = ((const float4*)bias)[sub];
    float4 o = make_float4(bb.x + dv * acc.x, bb.y + dv * acc.y,
                           bb.z + dv * acc.z, bb.w + dv * acc.w);
    red_add_v4(g_pool + (size_t)g * 64 + sub * 4, o);
}

// ---------------- final: out = (pool / max(cnt,1)) @ Wl + bl ----------------
__global__ void final_kernel(const float* __restrict__ Wl,
                             const float* __restrict__ bl,
                             float* __restrict__ out) {
    int g = blockIdx.x;
    int n = threadIdx.x;
    __shared__ float ps[64];
    float inv = 1.0f / fmaxf(g_cnt[g], 1.0f);
    ps[n] = g_pool[g * 64 + n] * inv;
    __syncthreads();
    float acc = bl[n];
    #pragma unroll
    for (int k = 0; k < 64; k++) acc += ps[k] * Wl[k * 64 + n];
    out[g * 64 + n] = acc;
}

// ---------------- launch ----------------
extern "C" void kernel_launch(void* const* d_in, const int* in_sizes, int n_in,
                              void* d_out, int out_size) {
    const float* x    = (const float*)d_in[0];
    const int*   ei32 = (const int*)d_in[1];
    const int*   b32  = (const int*)d_in[2];
    const float* W1   = (const float*)d_in[3];
    const float* b1   = (const float*)d_in[4];
    const float* W2   = (const float*)d_in[5];
    const float* b2   = (const float*)d_in[6];
    const float* Wl   = (const float*)d_in[7];
    const float* bl   = (const float*)d_in[8];
    float* out = (float*)d_out;

    __half *p_h1, *p_agg1, *p_hs2, *p_w1t, *p_w2t;
    cudaGetSymbolAddress((void**)&p_h1,   g_h1);
    cudaGetSymbolAddress((void**)&p_agg1, g_agg1);
    cudaGetSymbolAddress((void**)&p_hs2,  g_hs2);
    cudaGetSymbolAddress((void**)&p_w1t,  g_w1t);
    cudaGetSymbolAddress((void**)&p_w2t,  g_w2t);

    const int SMEM1 = (64 + 128) * 136 * 2;   // 52224
    const int SMEM2 = (64 + 64) * 136 * 2;    // 34816
    cudaFuncSetAttribute((const void*)mma_gemm_kernel<128, 64, false, false>,
                         cudaFuncAttributeMaxDynamicSharedMemorySize, SMEM1);
    cudaFuncSetAttribute((const void*)mma_gemm_kernel<64, 32, true, true>,
                         cudaFuncAttributeMaxDynamicSharedMemorySize, SMEM2);

    const int GRID_M = (N_NODES + 63) / 64;   // 782

    // ---- fork: weight prep + GEMM1 on side stream ----
    cudaEventRecord(s_ev_fork, 0);
    cudaStreamWaitEvent(s_side, s_ev_fork, 0);
    prep_w_kernel<<<64, 256, 0, s_side>>>(W1, W2);
    mma_gemm_kernel<128, 64, false, false>
        <<<GRID_M, 256, SMEM1, s_side>>>(x, p_w1t, p_h1, N_NODES);
    cudaEventRecord(s_ev_gemm1, s_side);

    // ---- main stream: CSR build ----
    detect_zero_kernel<<<NBLK, 256>>>(ei32, b32);
    convert_kernel<<<(N_EDGES + 255) / 256, 256>>>(ei32, b32);
    scanA_kernel<<<NBLK, 256>>>();
    scanC_kernel<<<NBLK, 256>>>();
    scatter_kernel<<<(N_EDGES + 255) / 256, 256>>>();

    // ---- join: gather needs CSR + h1 ----
    cudaStreamWaitEvent(0, s_ev_gemm1, 0);
    gather128_kernel<<<(N_NODES * 32 + 255) / 256, 256>>>(p_h1, b1, p_agg1);

    // layer 2 (+ fused pool); W2t ready (ordered behind s_ev_gemm1)
    mma_gemm_kernel<64, 32, true, true>
        <<<GRID_M, 256, SMEM2>>>(p_agg1, p_w2t, p_hs2, N_NODES);
    gather64_pool_kernel<<<(N_NODES * 16 + 255) / 256, 256>>>(p_hs2, b2);

    // final linear
    final_kernel<<<NUM_GRAPHS, 64>>>(Wl, bl, out);
}